// round 14
// baseline (speedup 1.0000x reference)
#include <cuda_runtime.h>
#include <cstdint>

#define B 16
#define S 4096
#define E 2048
#define WIN 64
#define ROWS (B * S)
#define NWIN (S - WIN + 1)     // 4033
#define CHUNKS 16
#define WPB 256                 // window starts per chunk
#define EPI_BLOCKS (B * CHUNKS) // 256
#define DOT_BLOCKS (ROWS / 8)   // 8192
#define BLK_PER_BAT (DOT_BLOCKS / B)  // 512

__device__ float g_scores[ROWS];
__device__ float g_part[EPI_BLOCKS];
__device__ int   g_cnt_dot[B];  // zero-init; reset by last epilogue block
__device__ int   g_cnt_epi;     // zero-init; reset by last epilogue block

// ---------------------------------------------------------------------------
// Kernel 1: EXACT R3 dot hot loop; adds per-batch release-count at block end.
// ---------------------------------------------------------------------------
__global__ __launch_bounds__(256) void dot_kernel(
    const float* __restrict__ x,
    const int*   __restrict__ mask,   // int32 {0,1} or float32 {0.,1.} bit patterns
    const float* __restrict__ W,
    const float* __restrict__ bias)
{
    const int warp = (blockIdx.x * blockDim.x + threadIdx.x) >> 5;  // row id
    const int lane = threadIdx.x & 31;

    const float4* __restrict__ xr = reinterpret_cast<const float4*>(x) + (size_t)warp * (E / 4);
    const float4* __restrict__ Wv = reinterpret_cast<const float4*>(W);

    float s0 = 0.f, s1 = 0.f, s2 = 0.f, s3 = 0.f;
    #pragma unroll
    for (int i = 0; i < 16; i += 4) {
        float4 a0 = xr[lane + (i + 0) * 32];
        float4 a1 = xr[lane + (i + 1) * 32];
        float4 a2 = xr[lane + (i + 2) * 32];
        float4 a3 = xr[lane + (i + 3) * 32];
        float4 w0 = Wv[lane + (i + 0) * 32];
        float4 w1 = Wv[lane + (i + 1) * 32];
        float4 w2 = Wv[lane + (i + 2) * 32];
        float4 w3 = Wv[lane + (i + 3) * 32];
        s0 += a0.x * w0.x + a0.y * w0.y + a0.z * w0.z + a0.w * w0.w;
        s1 += a1.x * w1.x + a1.y * w1.y + a1.z * w1.z + a1.w * w1.w;
        s2 += a2.x * w2.x + a2.y * w2.y + a2.z * w2.z + a2.w * w2.w;
        s3 += a3.x * w3.x + a3.y * w3.y + a3.z * w3.z + a3.w * w3.w;
    }
    float sum = (s0 + s1) + (s2 + s3);

    #pragma unroll
    for (int o = 16; o > 0; o >>= 1)
        sum += __shfl_xor_sync(0xFFFFFFFFu, sum, o);

    if (lane == 0) {
        float tot = sum + bias[0];
        g_scores[warp] = (mask[warp] != 0) ? tot : 0.0f;
    }

    // Release this block's 8 rows to the dependent epilogue.
    __syncthreads();
    if (threadIdx.x == 0) {
        __threadfence();
        atomicAdd(&g_cnt_dot[blockIdx.x / BLK_PER_BAT], 1);
    }

    // Allow the PDL-dependent epilogue grid to begin dispatching.
    cudaTriggerProgrammaticLaunchCompletion();
}

// ---------------------------------------------------------------------------
// Kernel 2: epilogue (PDL). No grid-wide sync: waits only on its batch's
// counter. Blocks become resident during the dot tail wave, so spins are
// short and never overlap the bandwidth-critical streaming phase.
// ---------------------------------------------------------------------------
__global__ __launch_bounds__(256) void epilogue_kernel(float* __restrict__ out)
{
    const int chunk = blockIdx.x;
    const int b     = blockIdx.y;
    const int t     = threadIdx.x;
    const int base  = chunk * WPB;

    // Wait until all 512 dot blocks of this batch have released.
    if (t == 0) {
        while (atomicAdd(&g_cnt_dot[b], 0) < BLK_PER_BAT)
            __nanosleep(100);
    }
    __syncthreads();
    __threadfence();   // acquire: order score reads after counter observe

    __shared__ float sm[WPB + WIN - 1];   // 319 floats
    const float* __restrict__ src = g_scores + (size_t)b * S;
    for (int i = t; i < WPB + WIN - 1; i += 256) {
        int idx = base + i;
        sm[i] = (idx < S) ? __ldcg(&src[idx]) : 0.0f;
    }
    __syncthreads();

    float best = -3.4e38f;
    if (base + t < NWIN) {
        float acc = 0.0f;
        #pragma unroll
        for (int k = 0; k < WIN; k++) acc += sm[t + k];
        best = acc;
    }

    #pragma unroll
    for (int o = 16; o > 0; o >>= 1)
        best = fmaxf(best, __shfl_xor_sync(0xFFFFFFFFu, best, o));

    __shared__ float pm[8];
    __shared__ int   is_last;
    if ((t & 31) == 0) pm[t >> 5] = best;
    __syncthreads();

    if (t == 0) {
        float m = pm[0];
        #pragma unroll
        for (int i = 1; i < 8; i++) m = fmaxf(m, pm[i]);
        g_part[b * CHUNKS + chunk] = m;
        __threadfence();
        int prev = atomicAdd(&g_cnt_epi, 1);
        is_last = (prev == EPI_BLOCKS - 1) ? 1 : 0;
    }
    __syncthreads();
    if (!is_last) return;

    // ---- last block: final 256-way max -> out[B], reset counters ----
    __threadfence();
    float v = g_part[t];                       // t = b*16 + c
    #pragma unroll
    for (int o = 8; o > 0; o >>= 1)
        v = fmaxf(v, __shfl_xor_sync(0xFFFFFFFFu, v, o));
    if ((t & 15) == 0)
        out[t >> 4] = v / (float)WIN;
    if (t < B) g_cnt_dot[t] = 0;               // reset for graph replay
    if (t == 0) g_cnt_epi = 0;
}

extern "C" void kernel_launch(void* const* d_in, const int* in_sizes, int n_in,
                              void* d_out, int out_size)
{
    const float* x    = (const float*)d_in[0];
    const int*   mask = (const int*)  d_in[1];
    const float* W    = (const float*)d_in[2];
    const float* bias = (const float*)d_in[3];
    float*       out  = (float*)d_out;

    dot_kernel<<<DOT_BLOCKS, 256>>>(x, mask, W, bias);   // 8 warps/block, 1 row/warp

    // Epilogue with Programmatic Stream Serialization (PDL).
    cudaLaunchConfig_t cfg = {};
    cfg.gridDim  = dim3(CHUNKS, B);
    cfg.blockDim = dim3(256);
    cfg.dynamicSmemBytes = 0;
    cfg.stream = 0;
    cudaLaunchAttribute attr[1];
    attr[0].id = cudaLaunchAttributeProgrammaticStreamSerialization;
    attr[0].val.programmaticStreamSerializationAllowed = 1;
    cfg.attrs = attr;
    cfg.numAttrs = 1;
    cudaLaunchKernelEx(&cfg, epilogue_kernel, out);
}

// round 15
// speedup vs baseline: 1.0481x; 1.0481x over previous
#include <cuda_runtime.h>
#include <cstdint>

#define B 16
#define S 4096
#define E 2048
#define WIN 64
#define ROWS (B * S)
#define NWIN (S - WIN + 1)     // 4033
#define DOT_BLOCKS (ROWS / 8)  // 8192
#define EPI_THREADS 1024
#define PASSES 4               // 4 * 1024 = 4096 >= NWIN

__device__ float g_scores[ROWS];

// ---------------------------------------------------------------------------
// Kernel 1: EXACT R3/R13 dot kernel + PDL trigger. Do not touch.
// ---------------------------------------------------------------------------
__global__ __launch_bounds__(256) void dot_kernel(
    const float* __restrict__ x,
    const int*   __restrict__ mask,   // int32 {0,1} or float32 {0.,1.} bit patterns
    const float* __restrict__ W,
    const float* __restrict__ bias)
{
    const int warp = (blockIdx.x * blockDim.x + threadIdx.x) >> 5;  // row id
    const int lane = threadIdx.x & 31;

    const float4* __restrict__ xr = reinterpret_cast<const float4*>(x) + (size_t)warp * (E / 4);
    const float4* __restrict__ Wv = reinterpret_cast<const float4*>(W);

    float s0 = 0.f, s1 = 0.f, s2 = 0.f, s3 = 0.f;
    #pragma unroll
    for (int i = 0; i < 16; i += 4) {
        float4 a0 = xr[lane + (i + 0) * 32];
        float4 a1 = xr[lane + (i + 1) * 32];
        float4 a2 = xr[lane + (i + 2) * 32];
        float4 a3 = xr[lane + (i + 3) * 32];
        float4 w0 = Wv[lane + (i + 0) * 32];
        float4 w1 = Wv[lane + (i + 1) * 32];
        float4 w2 = Wv[lane + (i + 2) * 32];
        float4 w3 = Wv[lane + (i + 3) * 32];
        s0 += a0.x * w0.x + a0.y * w0.y + a0.z * w0.z + a0.w * w0.w;
        s1 += a1.x * w1.x + a1.y * w1.y + a1.z * w1.z + a1.w * w1.w;
        s2 += a2.x * w2.x + a2.y * w2.y + a2.z * w2.z + a2.w * w2.w;
        s3 += a3.x * w3.x + a3.y * w3.y + a3.z * w3.z + a3.w * w3.w;
    }
    float sum = (s0 + s1) + (s2 + s3);

    #pragma unroll
    for (int o = 16; o > 0; o >>= 1)
        sum += __shfl_xor_sync(0xFFFFFFFFu, sum, o);

    if (lane == 0) {
        float tot = sum + bias[0];
        g_scores[warp] = (mask[warp] != 0) ? tot : 0.0f;
    }

    // Allow the PDL-dependent epilogue grid to begin dispatching.
    cudaTriggerProgrammaticLaunchCompletion();
}

// ---------------------------------------------------------------------------
// Kernel 2: epilogue (PDL). 16 blocks x 1024 threads, one batch per block.
// Stateless: no global scratch, no atomics, no reset. Conflict-free LDS:
// at each pass p, lanes read sm[t + 1024p + k] (stride-1).
// ---------------------------------------------------------------------------
__global__ __launch_bounds__(EPI_THREADS) void epilogue_kernel(float* __restrict__ out)
{
    // Wait for dot_kernel completion + memory flush (HW dependency).
    cudaGridDependencySynchronize();

    const int b = blockIdx.x;
    const int t = threadIdx.x;

    __shared__ float sm[S];                      // 16 KB
    const float4* __restrict__ src =
        reinterpret_cast<const float4*>(g_scores + (size_t)b * S);
    reinterpret_cast<float4*>(sm)[t] = src[t];   // 1024 x 16B = 16 KB
    __syncthreads();

    float best = -3.4e38f;
    #pragma unroll
    for (int p = 0; p < PASSES; p++) {
        const int w = p * EPI_THREADS + t;
        if (w < NWIN) {
            float acc = 0.0f;
            #pragma unroll
            for (int k = 0; k < WIN; k++) acc += sm[w + k];
            best = fmaxf(best, acc);
        }
    }

    #pragma unroll
    for (int o = 16; o > 0; o >>= 1)
        best = fmaxf(best, __shfl_xor_sync(0xFFFFFFFFu, best, o));

    __shared__ float pm[32];
    if ((t & 31) == 0) pm[t >> 5] = best;
    __syncthreads();

    if (t < 32) {
        float m = pm[t];
        #pragma unroll
        for (int o = 16; o > 0; o >>= 1)
            m = fmaxf(m, __shfl_xor_sync(0xFFFFFFFFu, m, o));
        if (t == 0) out[b] = m / (float)WIN;
    }
}

extern "C" void kernel_launch(void* const* d_in, const int* in_sizes, int n_in,
                              void* d_out, int out_size)
{
    const float* x    = (const float*)d_in[0];
    const int*   mask = (const int*)  d_in[1];
    const float* W    = (const float*)d_in[2];
    const float* bias = (const float*)d_in[3];
    float*       out  = (float*)d_out;

    dot_kernel<<<DOT_BLOCKS, 256>>>(x, mask, W, bias);   // 8 warps/block, 1 row/warp

    // Epilogue with Programmatic Stream Serialization (PDL).
    cudaLaunchConfig_t cfg = {};
    cfg.gridDim  = dim3(B);
    cfg.blockDim = dim3(EPI_THREADS);
    cfg.dynamicSmemBytes = 0;
    cfg.stream = 0;
    cudaLaunchAttribute attr[1];
    attr[0].id = cudaLaunchAttributeProgrammaticStreamSerialization;
    attr[0].val.programmaticStreamSerializationAllowed = 1;
    cfg.attrs = attr;
    cfg.numAttrs = 1;
    cudaLaunchKernelEx(&cfg, epilogue_kernel, out);
}

// round 16
// speedup vs baseline: 1.0626x; 1.0138x over previous
#include <cuda_runtime.h>
#include <cstdint>

#define B 16
#define S 4096
#define E 2048
#define WIN 64
#define ROWS (B * S)
#define NWIN (S - WIN + 1)     // 4033
#define CHUNKS 16
#define WPB 256                 // window starts per chunk
#define EPI_BLOCKS (B * CHUNKS) // 256
#define DOT_BLOCKS (ROWS / 8)   // 8192

__device__ float g_scores[ROWS];
__device__ float g_part[EPI_BLOCKS];
__device__ int   g_cnt;         // zero-init; reset by last block each run

// ---------------------------------------------------------------------------
// Kernel 1: R3/R13 dot kernel; mask/bias loads hoisted before the main loop
// so their DRAM latency overlaps the streaming loads instead of appending
// to each warp's critical path. Hot loop body unchanged.
// ---------------------------------------------------------------------------
__global__ __launch_bounds__(256) void dot_kernel(
    const float* __restrict__ x,
    const int*   __restrict__ mask,   // int32 {0,1} or float32 {0.,1.} bit patterns
    const float* __restrict__ W,
    const float* __restrict__ bias)
{
    const int warp = (blockIdx.x * blockDim.x + threadIdx.x) >> 5;  // row id
    const int lane = threadIdx.x & 31;

    // Hoisted: in flight during the entire main loop.
    const int   mrow = __ldg(&mask[warp]);
    const float bval = __ldg(&bias[0]);

    const float4* __restrict__ xr = reinterpret_cast<const float4*>(x) + (size_t)warp * (E / 4);
    const float4* __restrict__ Wv = reinterpret_cast<const float4*>(W);

    float s0 = 0.f, s1 = 0.f, s2 = 0.f, s3 = 0.f;
    #pragma unroll
    for (int i = 0; i < 16; i += 4) {
        float4 a0 = xr[lane + (i + 0) * 32];
        float4 a1 = xr[lane + (i + 1) * 32];
        float4 a2 = xr[lane + (i + 2) * 32];
        float4 a3 = xr[lane + (i + 3) * 32];
        float4 w0 = Wv[lane + (i + 0) * 32];
        float4 w1 = Wv[lane + (i + 1) * 32];
        float4 w2 = Wv[lane + (i + 2) * 32];
        float4 w3 = Wv[lane + (i + 3) * 32];
        s0 += a0.x * w0.x + a0.y * w0.y + a0.z * w0.z + a0.w * w0.w;
        s1 += a1.x * w1.x + a1.y * w1.y + a1.z * w1.z + a1.w * w1.w;
        s2 += a2.x * w2.x + a2.y * w2.y + a2.z * w2.z + a2.w * w2.w;
        s3 += a3.x * w3.x + a3.y * w3.y + a3.z * w3.z + a3.w * w3.w;
    }
    float sum = (s0 + s1) + (s2 + s3);

    #pragma unroll
    for (int o = 16; o > 0; o >>= 1)
        sum += __shfl_xor_sync(0xFFFFFFFFu, sum, o);

    if (lane == 0) {
        float tot = sum + bval;
        g_scores[warp] = (mrow != 0) ? tot : 0.0f;
    }

    // Allow the PDL-dependent epilogue grid to begin dispatching.
    cudaTriggerProgrammaticLaunchCompletion();
}

// ---------------------------------------------------------------------------
// Kernel 2: R13 epilogue, bit-identical. grid=(CHUNKS,B), 256 threads.
// ---------------------------------------------------------------------------
__global__ __launch_bounds__(256) void epilogue_kernel(float* __restrict__ out)
{
    // Wait for dot_kernel completion + memory flush (HW dependency, not a spin).
    cudaGridDependencySynchronize();

    const int chunk = blockIdx.x;
    const int b     = blockIdx.y;
    const int t     = threadIdx.x;
    const int base  = chunk * WPB;

    __shared__ float sm[WPB + WIN - 1];   // 319 floats
    const float* __restrict__ src = g_scores + (size_t)b * S;
    for (int i = t; i < WPB + WIN - 1; i += 256) {
        int idx = base + i;
        sm[i] = (idx < S) ? src[idx] : 0.0f;
    }
    __syncthreads();

    float best = -3.4e38f;
    if (base + t < NWIN) {
        float acc = 0.0f;
        #pragma unroll
        for (int k = 0; k < WIN; k++) acc += sm[t + k];
        best = acc;
    }

    #pragma unroll
    for (int o = 16; o > 0; o >>= 1)
        best = fmaxf(best, __shfl_xor_sync(0xFFFFFFFFu, best, o));

    __shared__ float pm[8];
    __shared__ int   is_last;
    if ((t & 31) == 0) pm[t >> 5] = best;
    __syncthreads();

    if (t == 0) {
        float m = pm[0];
        #pragma unroll
        for (int i = 1; i < 8; i++) m = fmaxf(m, pm[i]);
        g_part[b * CHUNKS + chunk] = m;
        __threadfence();
        int prev = atomicAdd(&g_cnt, 1);
        is_last = (prev == EPI_BLOCKS - 1) ? 1 : 0;
    }
    __syncthreads();
    if (!is_last) return;

    // ---- last block: final 256-way max -> out[B] ----
    __threadfence();
    float v = g_part[t];                       // t = b*16 + c
    #pragma unroll
    for (int o = 8; o > 0; o >>= 1)
        v = fmaxf(v, __shfl_xor_sync(0xFFFFFFFFu, v, o));
    if ((t & 15) == 0)
        out[t >> 4] = v / (float)WIN;
    if (t == 0) g_cnt = 0;                     // reset for graph replay
}

extern "C" void kernel_launch(void* const* d_in, const int* in_sizes, int n_in,
                              void* d_out, int out_size)
{
    const float* x    = (const float*)d_in[0];
    const int*   mask = (const int*)  d_in[1];
    const float* W    = (const float*)d_in[2];
    const float* bias = (const float*)d_in[3];
    float*       out  = (float*)d_out;

    dot_kernel<<<DOT_BLOCKS, 256>>>(x, mask, W, bias);   // 8 warps/block, 1 row/warp

    // Epilogue with Programmatic Stream Serialization (PDL).
    cudaLaunchConfig_t cfg = {};
    cfg.gridDim  = dim3(CHUNKS, B);
    cfg.blockDim = dim3(256);
    cfg.dynamicSmemBytes = 0;
    cfg.stream = 0;
    cudaLaunchAttribute attr[1];
    attr[0].id = cudaLaunchAttributeProgrammaticStreamSerialization;
    attr[0].val.programmaticStreamSerializationAllowed = 1;
    cfg.attrs = attr;
    cfg.numAttrs = 1;
    cudaLaunchKernelEx(&cfg, epilogue_kernel, out);
}